// round 3
// baseline (speedup 1.0000x reference)
#include <cuda_runtime.h>
#include <math.h>

// Problem constants
constexpr int B_   = 4;
constexpr int N_   = 2048;
constexpr int D_   = 1024;     // D_IN == D_OUT == 1024
constexpr int MTOT = B_ * N_;  // 8192

// Scratch (static __device__ globals: allocation-free per harness rules)
__device__ float g_Q[(size_t)MTOT * D_];         // 32 MB
__device__ float g_K[(size_t)MTOT * D_];         // 32 MB
__device__ float g_V[(size_t)MTOT * D_];         // 32 MB
__device__ float g_S[(size_t)B_ * N_ * N_];      // 64 MB

#define BM 128
#define BN 128
#define BK 16
#define TM 8
#define TN 8
// 256 threads: 16x16 thread grid, 8x8 accumulators each.

// Generic tiled fp32 GEMM: C = A @ B (+bias), optionally B given as
// row-major [Nc x Kd] to be used transposed (TRANSB: C = A @ B^T).
// blockIdx.z selects a batch slice via the sA/sB/sC strides.
template<bool TRANSB, bool BIAS>
__global__ void __launch_bounds__(256, 2)
gemm_kernel(const float* __restrict__ Ag, const float* __restrict__ Bg,
            const float* __restrict__ bias, float* __restrict__ Cg,
            int M, int Nc, int Kd,
            long sA, long sB, long sC)
{
    __shared__ float As[2][BK][BM];
    __shared__ float Bs[2][BK][BN];

    const float* A  = Ag + (long)blockIdx.z * sA;
    const float* Bm = Bg + (long)blockIdx.z * sB;
    float*       C  = Cg + (long)blockIdx.z * sC;

    const int tid = threadIdx.x;
    const int m0  = blockIdx.y * BM;
    const int n0  = blockIdx.x * BN;

    // A-tile (and NT B-tile) loader indices: 128 rows x 16 cols, 2 float4/thread
    const int a_r = tid >> 2;          // 0..63
    const int a_c = (tid & 3) << 2;    // 0,4,8,12
    // NN B-tile loader: 16 rows x 128 cols, 2 float4/thread
    const int bn_r = tid >> 5;         // 0..7
    const int bn_c = (tid & 31) << 2;  // 0..124

    const int ty = tid >> 4, tx = tid & 15;
    const int rowb = ty * TM, colb = tx * TN;

    const float* Aptr = A + (long)(m0 + a_r) * Kd + a_c;
    const float* Bptr;
    if (TRANSB) Bptr = Bm + (long)(n0 + a_r) * Kd + a_c;        // B stored [Nc x Kd]
    else        Bptr = Bm + (long)bn_r * Nc + n0 + bn_c;        // B stored [Kd x Nc]

    float acc[TM][TN];
    #pragma unroll
    for (int i = 0; i < TM; i++)
        #pragma unroll
        for (int j = 0; j < TN; j++) acc[i][j] = 0.0f;

    float4 aR0, aR1, bR0, bR1;

    // ---- prologue: load K-tile 0 ----
    aR0 = *(const float4*)(Aptr);
    aR1 = *(const float4*)(Aptr + 64L * Kd);
    if (TRANSB) { bR0 = *(const float4*)(Bptr); bR1 = *(const float4*)(Bptr + 64L * Kd); }
    else        { bR0 = *(const float4*)(Bptr); bR1 = *(const float4*)(Bptr + 8L * Nc); }

    {
        const float* a0 = (const float*)&aR0; const float* a1 = (const float*)&aR1;
        #pragma unroll
        for (int i = 0; i < 4; i++) { As[0][a_c+i][a_r] = a0[i]; As[0][a_c+i][a_r+64] = a1[i]; }
        if (TRANSB) {
            const float* b0 = (const float*)&bR0; const float* b1 = (const float*)&bR1;
            #pragma unroll
            for (int i = 0; i < 4; i++) { Bs[0][a_c+i][a_r] = b0[i]; Bs[0][a_c+i][a_r+64] = b1[i]; }
        } else {
            *(float4*)&Bs[0][bn_r][bn_c]   = bR0;
            *(float4*)&Bs[0][bn_r+8][bn_c] = bR1;
        }
    }
    __syncthreads();

    const int nk = Kd / BK;
    for (int kt = 0; kt < nk; kt++) {
        const int cur = kt & 1;
        // prefetch next K-tile into registers (overlaps with compute)
        if (kt + 1 < nk) {
            const float* Ap = Aptr + (kt + 1) * BK;
            aR0 = *(const float4*)(Ap);
            aR1 = *(const float4*)(Ap + 64L * Kd);
            if (TRANSB) {
                const float* Bp = Bptr + (kt + 1) * BK;
                bR0 = *(const float4*)(Bp);
                bR1 = *(const float4*)(Bp + 64L * Kd);
            } else {
                const float* Bp = Bptr + (long)(kt + 1) * BK * Nc;
                bR0 = *(const float4*)(Bp);
                bR1 = *(const float4*)(Bp + 8L * Nc);
            }
        }
        // compute current tile
        #pragma unroll
        for (int kk = 0; kk < BK; kk++) {
            float4 av0 = *(const float4*)&As[cur][kk][rowb];
            float4 av1 = *(const float4*)&As[cur][kk][rowb + 4];
            float4 bv0 = *(const float4*)&Bs[cur][kk][colb];
            float4 bv1 = *(const float4*)&Bs[cur][kk][colb + 4];
            float a[TM] = {av0.x, av0.y, av0.z, av0.w, av1.x, av1.y, av1.z, av1.w};
            float b[TN] = {bv0.x, bv0.y, bv0.z, bv0.w, bv1.x, bv1.y, bv1.z, bv1.w};
            #pragma unroll
            for (int i = 0; i < TM; i++)
                #pragma unroll
                for (int j = 0; j < TN; j++)
                    acc[i][j] = fmaf(a[i], b[j], acc[i][j]);
        }
        // stage next tile into the other smem buffer
        if (kt + 1 < nk) {
            const int nxt = cur ^ 1;
            const float* a0 = (const float*)&aR0; const float* a1 = (const float*)&aR1;
            #pragma unroll
            for (int i = 0; i < 4; i++) { As[nxt][a_c+i][a_r] = a0[i]; As[nxt][a_c+i][a_r+64] = a1[i]; }
            if (TRANSB) {
                const float* b0 = (const float*)&bR0; const float* b1 = (const float*)&bR1;
                #pragma unroll
                for (int i = 0; i < 4; i++) { Bs[nxt][a_c+i][a_r] = b0[i]; Bs[nxt][a_c+i][a_r+64] = b1[i]; }
            } else {
                *(float4*)&Bs[nxt][bn_r][bn_c]   = bR0;
                *(float4*)&Bs[nxt][bn_r+8][bn_c] = bR1;
            }
            __syncthreads();
        }
    }

    // ---- epilogue ----
    #pragma unroll
    for (int i = 0; i < TM; i++) {
        float* crow = C + (long)(m0 + rowb + i) * Nc + n0 + colb;
        #pragma unroll
        for (int j = 0; j < TN; j += 4) {
            float4 v = make_float4(acc[i][j], acc[i][j+1], acc[i][j+2], acc[i][j+3]);
            if (BIAS) {
                const int nb = n0 + colb + j;
                v.x += bias[nb + 0];
                v.y += bias[nb + 1];
                v.z += bias[nb + 2];
                v.w += bias[nb + 3];
            }
            *(float4*)&crow[j] = v;
        }
    }
}

// Row softmax over S rows of length N_ (2048). One block per row, 256 threads.
__global__ void __launch_bounds__(256)
softmax_kernel(float* __restrict__ S)
{
    const long row = blockIdx.x;
    float* p = S + row * (long)N_;
    const int tid = threadIdx.x;

    float v[8];
    float mx = -1e30f;
    #pragma unroll
    for (int i = 0; i < 8; i++) { v[i] = p[tid + i * 256]; mx = fmaxf(mx, v[i]); }

    __shared__ float redm[8];
    __shared__ float reds[8];

    #pragma unroll
    for (int o = 16; o; o >>= 1) mx = fmaxf(mx, __shfl_xor_sync(0xffffffffu, mx, o));
    if ((tid & 31) == 0) redm[tid >> 5] = mx;
    __syncthreads();
    if (tid == 0) {
        float m = redm[0];
        #pragma unroll
        for (int i = 1; i < 8; i++) m = fmaxf(m, redm[i]);
        redm[0] = m;
    }
    __syncthreads();
    mx = redm[0];

    float s = 0.0f;
    #pragma unroll
    for (int i = 0; i < 8; i++) { v[i] = __expf(v[i] - mx); s += v[i]; }
    #pragma unroll
    for (int o = 16; o; o >>= 1) s += __shfl_xor_sync(0xffffffffu, s, o);
    if ((tid & 31) == 0) reds[tid >> 5] = s;
    __syncthreads();
    if (tid == 0) {
        float m = 0.0f;
        #pragma unroll
        for (int i = 0; i < 8; i++) m += reds[i];
        reds[0] = m;
    }
    __syncthreads();
    const float inv = 1.0f / reds[0];

    #pragma unroll
    for (int i = 0; i < 8; i++) p[tid + i * 256] = v[i] * inv;
}

extern "C" void kernel_launch(void* const* d_in, const int* in_sizes, int n_in,
                              void* d_out, int out_size)
{
    const float* X  = (const float*)d_in[0];
    const float* Wq = (const float*)d_in[1];
    const float* bq = (const float*)d_in[2];
    const float* Wk = (const float*)d_in[3];
    const float* bk = (const float*)d_in[4];
    const float* Wv = (const float*)d_in[5];
    const float* bv = (const float*)d_in[6];
    float* out = (float*)d_out;

    float *Q, *Kp, *V, *S;
    cudaGetSymbolAddress((void**)&Q,  g_Q);
    cudaGetSymbolAddress((void**)&Kp, g_K);
    cudaGetSymbolAddress((void**)&V,  g_V);
    cudaGetSymbolAddress((void**)&S,  g_S);

    dim3 blk(256);

    // 1) QKV projections: [8192,1024] @ [1024,1024] + bias
    dim3 g1(D_ / BN, MTOT / BM, 1);
    gemm_kernel<false, true><<<g1, blk>>>(X, Wq, bq, Q,  MTOT, D_, D_, 0, 0, 0);
    gemm_kernel<false, true><<<g1, blk>>>(X, Wk, bk, Kp, MTOT, D_, D_, 0, 0, 0);
    gemm_kernel<false, true><<<g1, blk>>>(X, Wv, bv, V,  MTOT, D_, D_, 0, 0, 0);

    // 2) S = Q @ K^T per batch (NT GEMM, batched over z)
    dim3 g2(N_ / BN, N_ / BM, B_);
    gemm_kernel<true, false><<<g2, blk>>>(Q, Kp, nullptr, S, N_, N_, D_,
                                          (long)N_ * D_, (long)N_ * D_, (long)N_ * N_);

    // 3) row softmax over S
    softmax_kernel<<<B_ * N_, 256>>>(S);

    // 4) out = P @ V per batch (NN GEMM, batched over z)
    dim3 g3(D_ / BN, N_ / BM, B_);
    gemm_kernel<false, false><<<g3, blk>>>(S, V, nullptr, out, N_, D_, N_,
                                           (long)N_ * N_, (long)N_ * D_, (long)N_ * D_);
}

// round 5
// speedup vs baseline: 1.4390x; 1.4390x over previous
#include <cuda_runtime.h>
#include <cuda_bf16.h>
#include <cstdint>
#include <math.h>

// Problem constants
constexpr int B_   = 4;
constexpr int N_   = 2048;
constexpr int D_   = 1024;
constexpr int MTOT = B_ * N_;  // 8192

// ---------------- scratch (static __device__, allocation-free) ----------------
__device__ __align__(1024) __nv_bfloat16 g_Xh[(size_t)MTOT * D_];
__device__ __align__(1024) __nv_bfloat16 g_Xl[(size_t)MTOT * D_];
__device__ __align__(1024) __nv_bfloat16 g_Qh[(size_t)MTOT * D_];
__device__ __align__(1024) __nv_bfloat16 g_Ql[(size_t)MTOT * D_];
__device__ __align__(1024) __nv_bfloat16 g_Kh[(size_t)MTOT * D_];
__device__ __align__(1024) __nv_bfloat16 g_Kl[(size_t)MTOT * D_];
__device__ __align__(1024) __nv_bfloat16 g_Vth[(size_t)D_ * MTOT];   // V^T [e][m]
__device__ __align__(1024) __nv_bfloat16 g_Vtl[(size_t)D_ * MTOT];
__device__ __align__(1024) __nv_bfloat16 g_Wqth[(size_t)D_ * D_];    // W^T [e][d]
__device__ __align__(1024) __nv_bfloat16 g_Wqtl[(size_t)D_ * D_];
__device__ __align__(1024) __nv_bfloat16 g_Wkth[(size_t)D_ * D_];
__device__ __align__(1024) __nv_bfloat16 g_Wktl[(size_t)D_ * D_];
__device__ __align__(1024) __nv_bfloat16 g_Wvth[(size_t)D_ * D_];
__device__ __align__(1024) __nv_bfloat16 g_Wvtl[(size_t)D_ * D_];
__device__ __align__(1024) float         g_S [(size_t)B_ * N_ * N_]; // 64 MB
__device__ __align__(1024) __nv_bfloat16 g_Ph[(size_t)B_ * N_ * N_];
__device__ __align__(1024) __nv_bfloat16 g_Pl[(size_t)B_ * N_ * N_];

// ---------------- helpers (plain sm_80-level PTX only; no 'a' features) -------
__device__ __forceinline__ uint32_t s2u(const void* p) {
    uint32_t a;
    asm("{ .reg .u64 t; cvta.to.shared.u64 t, %1; cvt.u32.u64 %0, t; }" : "=r"(a) : "l"(p));
    return a;
}
__device__ __forceinline__ void cpasync16(uint32_t dst, const void* src) {
    asm volatile("cp.async.cg.shared.global [%0], [%1], 16;" :: "r"(dst), "l"(src));
}
__device__ __forceinline__ void ldm4(uint32_t (&r)[4], uint32_t addr) {
    asm volatile("ldmatrix.sync.aligned.m8n8.x4.shared.b16 {%0,%1,%2,%3}, [%4];"
                 : "=r"(r[0]), "=r"(r[1]), "=r"(r[2]), "=r"(r[3]) : "r"(addr));
}
__device__ __forceinline__ void mma16816(float (&c)[4], const uint32_t* a,
                                         uint32_t b0, uint32_t b1) {
    asm volatile(
        "mma.sync.aligned.m16n8k16.row.col.f32.bf16.bf16.f32 "
        "{%0,%1,%2,%3}, {%4,%5,%6,%7}, {%8,%9}, {%0,%1,%2,%3};"
        : "+f"(c[0]), "+f"(c[1]), "+f"(c[2]), "+f"(c[3])
        : "r"(a[0]), "r"(a[1]), "r"(a[2]), "r"(a[3]), "r"(b0), "r"(b1));
}
// Tile row = 32 bf16 = 64B; swizzle 16B chunk index within row for conflict-free ldmatrix
__device__ __forceinline__ uint32_t swoff(int row, int kb) {
    return (uint32_t)(row * 64 + ((kb ^ ((row >> 1) & 3)) << 4));
}

constexpr int TILE_BYTES = 128 * 32 * 2;     // 8 KB: 128 rows x 32 bf16
constexpr int STAGES     = 3;
constexpr size_t SMEM_BYTES = (size_t)STAGES * 4 * TILE_BYTES;  // 96 KB

// ================= split-bf16 mma.sync GEMM =================
// C[m0+m, n0+n] = sum_k (Ah+Al)[m,k] * (Bh+Bl)[n,k]   (NT, both K-major)
// OUTMODE: 0 = fp32 C, 1 = split hi/lo bf16 C. BIASMODE: 0 none, 1 by col, 2 by row.
template<int OUTMODE, int BIASMODE>
__global__ void __launch_bounds__(256, 1)
tc_gemm(const __nv_bfloat16* __restrict__ Ah, const __nv_bfloat16* __restrict__ Al,
        int lda, long sA,
        const __nv_bfloat16* __restrict__ Bh, const __nv_bfloat16* __restrict__ Bl,
        int ldb, long sB,
        float* __restrict__ Cf, __nv_bfloat16* __restrict__ Ch, __nv_bfloat16* __restrict__ Cl,
        int ldc, long sC, const float* __restrict__ bias, int Kd)
{
    extern __shared__ __align__(128) char dsm[];
    const uint32_t base = s2u(dsm);

    const int tid = threadIdx.x, wid = tid >> 5, lid = tid & 31;
    const int wm = wid >> 2, wn = wid & 3;       // warp grid 2 x 4, warp tile 64x32
    const int m0 = blockIdx.y * 128, n0 = blockIdx.x * 128;
    const long z = blockIdx.z;
    Ah += z * sA; Al += z * sA; Bh += z * sB; Bl += z * sB;

    const __nv_bfloat16* srcs[4] = {
        Ah + (long)m0 * lda, Al + (long)m0 * lda,
        Bh + (long)n0 * ldb, Bl + (long)n0 * ldb };
    const int ldsv[4] = { lda, lda, ldb, ldb };

    auto load_chunk = [&](int chunk, int stage) {
        #pragma unroll
        for (int p = 0; p < 4; p++) {
            const __nv_bfloat16* s = srcs[p] + chunk * 32;
            const int ld = ldsv[p];
            const uint32_t tb = base + (uint32_t)((stage * 4 + p) * TILE_BYTES);
            #pragma unroll
            for (int i = 0; i < 2; i++) {
                int o = i * 256 + tid;          // 512 chunks of 16B
                int r = o >> 2, kb = o & 3;
                cpasync16(tb + swoff(r, kb), s + (long)r * ld + kb * 8);
            }
        }
        asm volatile("cp.async.commit_group;" ::: "memory");
    };

    float acc[4][4][4];
    #pragma unroll
    for (int i = 0; i < 4; i++)
        #pragma unroll
        for (int t = 0; t < 4; t++)
            #pragma unroll
            for (int j = 0; j < 4; j++) acc[i][t][j] = 0.0f;

    const int nk = Kd / 32;
    load_chunk(0, 0); load_chunk(1, 1); load_chunk(2, 2);

    const int rA  = (lid & 7) + ((lid >> 3) & 1) * 8;  // ldmatrix row-in-16
    const int kbh = (lid >> 4) & 1;                    // ldmatrix k-half

    for (int k = 0; k < nk; k++) {
        if (k + 3 <= nk)      asm volatile("cp.async.wait_group 2;" ::: "memory");
        else if (k + 2 == nk) asm volatile("cp.async.wait_group 1;" ::: "memory");
        else                  asm volatile("cp.async.wait_group 0;" ::: "memory");
        __syncthreads();

        const int stage = k % STAGES;
        const uint32_t tAh = base + (uint32_t)((stage * 4 + 0) * TILE_BYTES);
        const uint32_t tAl = base + (uint32_t)((stage * 4 + 1) * TILE_BYTES);
        const uint32_t tBh = base + (uint32_t)((stage * 4 + 2) * TILE_BYTES);
        const uint32_t tBl = base + (uint32_t)((stage * 4 + 3) * TILE_BYTES);

        #pragma unroll
        for (int p = 0; p < 2; p++) {            // two k16 steps per 32-chunk
            const int kb = 2 * p + kbh;
            uint32_t fAh[4][4], fAl[4][4], fBh[2][4], fBl[2][4];
            #pragma unroll
            for (int i = 0; i < 4; i++) {
                const uint32_t o = swoff(wm * 64 + i * 16 + rA, kb);
                ldm4(fAh[i], tAh + o);
                ldm4(fAl[i], tAl + o);
            }
            #pragma unroll
            for (int q = 0; q < 2; q++) {
                const uint32_t o = swoff(wn * 32 + q * 16 + rA, kb);
                ldm4(fBh[q], tBh + o);
                ldm4(fBl[q], tBl + o);
            }
            #pragma unroll
            for (int i = 0; i < 4; i++)
                #pragma unroll
                for (int nt = 0; nt < 4; nt++) {
                    const int q = nt >> 1, sx = nt & 1;
                    mma16816(acc[i][nt], fAh[i], fBh[q][sx], fBh[q][sx + 2]);
                    mma16816(acc[i][nt], fAh[i], fBl[q][sx], fBl[q][sx + 2]);
                    mma16816(acc[i][nt], fAl[i], fBh[q][sx], fBh[q][sx + 2]);
                }
        }
        __syncthreads();
        if (k + 3 < nk) load_chunk(k + 3, (k + 3) % STAGES);
    }

    // ---------------- epilogue: direct register -> gmem ----------------
    #pragma unroll
    for (int i = 0; i < 4; i++)
        #pragma unroll
        for (int nt = 0; nt < 4; nt++) {
            const int row = m0 + wm * 64 + i * 16 + (lid >> 2);
            const int col = n0 + wn * 32 + nt * 8 + 2 * (lid & 3);
            float v0 = acc[i][nt][0], v1 = acc[i][nt][1];
            float v2 = acc[i][nt][2], v3 = acc[i][nt][3];
            if (BIASMODE == 1) {
                const float b0 = bias[col], b1 = bias[col + 1];
                v0 += b0; v1 += b1; v2 += b0; v3 += b1;
            } else if (BIASMODE == 2) {
                const float b0 = bias[row], b1 = bias[row + 8];
                v0 += b0; v1 += b0; v2 += b1; v3 += b1;
            }
            const long o0 = (long)row * ldc + col + z * sC;
            const long o1 = o0 + 8L * ldc;
            if (OUTMODE == 0) {
                *(float2*)(Cf + o0) = make_float2(v0, v1);
                *(float2*)(Cf + o1) = make_float2(v2, v3);
            } else {
                __nv_bfloat16 h0 = __float2bfloat16(v0), h1 = __float2bfloat16(v1);
                __nv_bfloat16 h2 = __float2bfloat16(v2), h3 = __float2bfloat16(v3);
                __nv_bfloat16 l0 = __float2bfloat16(v0 - __bfloat162float(h0));
                __nv_bfloat16 l1 = __float2bfloat16(v1 - __bfloat162float(h1));
                __nv_bfloat16 l2 = __float2bfloat16(v2 - __bfloat162float(h2));
                __nv_bfloat16 l3 = __float2bfloat16(v3 - __bfloat162float(h3));
                __nv_bfloat162 ph0; ph0.x = h0; ph0.y = h1;
                __nv_bfloat162 ph1; ph1.x = h2; ph1.y = h3;
                __nv_bfloat162 pl0; pl0.x = l0; pl0.y = l1;
                __nv_bfloat162 pl1; pl1.x = l2; pl1.y = l3;
                *(__nv_bfloat162*)(Ch + o0) = ph0;
                *(__nv_bfloat162*)(Ch + o1) = ph1;
                *(__nv_bfloat162*)(Cl + o0) = pl0;
                *(__nv_bfloat162*)(Cl + o1) = pl1;
            }
        }
}

// ================= prep kernels =================
__global__ void __launch_bounds__(256)
split_x_kernel(const float* __restrict__ X, __nv_bfloat16* __restrict__ Xh,
               __nv_bfloat16* __restrict__ Xl)
{
    const long i = ((long)blockIdx.x * 256 + threadIdx.x) * 4;
    float4 v = *(const float4*)(X + i);
    float vv[4] = { v.x, v.y, v.z, v.w };
    __nv_bfloat16 h[4], l[4];
    #pragma unroll
    for (int j = 0; j < 4; j++) {
        h[j] = __float2bfloat16(vv[j]);
        l[j] = __float2bfloat16(vv[j] - __bfloat162float(h[j]));
    }
    __nv_bfloat162 h01, h23, l01, l23;
    h01.x = h[0]; h01.y = h[1]; h23.x = h[2]; h23.y = h[3];
    l01.x = l[0]; l01.y = l[1]; l23.x = l[2]; l23.y = l[3];
    *(__nv_bfloat162*)(Xh + i)     = h01;
    *(__nv_bfloat162*)(Xh + i + 2) = h23;
    *(__nv_bfloat162*)(Xl + i)     = l01;
    *(__nv_bfloat162*)(Xl + i + 2) = l23;
}

// Transpose + split 1024x1024 weights: T[e][d] = W[d][e]
__global__ void __launch_bounds__(256)
transpose_split_kernel(const float* __restrict__ W0, const float* __restrict__ W1,
                       const float* __restrict__ W2,
                       __nv_bfloat16* __restrict__ T0h, __nv_bfloat16* __restrict__ T0l,
                       __nv_bfloat16* __restrict__ T1h, __nv_bfloat16* __restrict__ T1l,
                       __nv_bfloat16* __restrict__ T2h, __nv_bfloat16* __restrict__ T2l)
{
    __shared__ float t[32][33];
    const float* W = (blockIdx.z == 0) ? W0 : (blockIdx.z == 1) ? W1 : W2;
    __nv_bfloat16* Th = (blockIdx.z == 0) ? T0h : (blockIdx.z == 1) ? T1h : T2h;
    __nv_bfloat16* Tl = (blockIdx.z == 0) ? T0l : (blockIdx.z == 1) ? T1l : T2l;

    const int tx = threadIdx.x, ty = threadIdx.y;       // block 32x8
    const int e = blockIdx.x * 32 + tx;
    const int d0 = blockIdx.y * 32;
    #pragma unroll
    for (int i = ty; i < 32; i += 8)
        t[i][tx] = W[(long)(d0 + i) * D_ + e];
    __syncthreads();
    const int eo = blockIdx.x * 32;
    const int d = d0 + tx;
    #pragma unroll
    for (int i = ty; i < 32; i += 8) {
        float w = t[tx][i];
        __nv_bfloat16 h = __float2bfloat16(w);
        __nv_bfloat16 l = __float2bfloat16(w - __bfloat162float(h));
        Th[(long)(eo + i) * D_ + d] = h;
        Tl[(long)(eo + i) * D_ + d] = l;
    }
}

// Row softmax over S (length 2048), write split-bf16 P.
__global__ void __launch_bounds__(256)
softmax_split_kernel(const float* __restrict__ S, __nv_bfloat16* __restrict__ Ph,
                     __nv_bfloat16* __restrict__ Pl)
{
    const long row = blockIdx.x;
    const float* p = S + row * (long)N_;
    const int tid = threadIdx.x;

    float v[8];
    float mx = -1e30f;
    #pragma unroll
    for (int i = 0; i < 8; i++) { v[i] = p[tid + i * 256]; mx = fmaxf(mx, v[i]); }

    __shared__ float redm[8], reds[8];
    #pragma unroll
    for (int o = 16; o; o >>= 1) mx = fmaxf(mx, __shfl_xor_sync(0xffffffffu, mx, o));
    if ((tid & 31) == 0) redm[tid >> 5] = mx;
    __syncthreads();
    if (tid == 0) {
        float m = redm[0];
        #pragma unroll
        for (int i = 1; i < 8; i++) m = fmaxf(m, redm[i]);
        redm[0] = m;
    }
    __syncthreads();
    mx = redm[0];

    float s = 0.0f;
    #pragma unroll
    for (int i = 0; i < 8; i++) { v[i] = __expf(v[i] - mx); s += v[i]; }
    #pragma unroll
    for (int o = 16; o; o >>= 1) s += __shfl_xor_sync(0xffffffffu, s, o);
    if ((tid & 31) == 0) reds[tid >> 5] = s;
    __syncthreads();
    if (tid == 0) {
        float m = 0.0f;
        #pragma unroll
        for (int i = 0; i < 8; i++) m += reds[i];
        reds[0] = m;
    }
    __syncthreads();
    const float inv = 1.0f / reds[0];

    #pragma unroll
    for (int i = 0; i < 8; i++) {
        float w = v[i] * inv;
        __nv_bfloat16 h = __float2bfloat16(w);
        __nv_bfloat16 l = __float2bfloat16(w - __bfloat162float(h));
        Ph[row * (long)N_ + tid + i * 256] = h;
        Pl[row * (long)N_ + tid + i * 256] = l;
    }
}

// ================= host glue =================
extern "C" void kernel_launch(void* const* d_in, const int* in_sizes, int n_in,
                              void* d_out, int out_size)
{
    const float* X  = (const float*)d_in[0];
    const float* Wq = (const float*)d_in[1];
    const float* bq = (const float*)d_in[2];
    const float* Wk = (const float*)d_in[3];
    const float* bk = (const float*)d_in[4];
    const float* Wv = (const float*)d_in[5];
    const float* bv = (const float*)d_in[6];
    float* out = (float*)d_out;

    __nv_bfloat16 *Xh, *Xl, *Qh, *Ql, *Kh, *Kl, *Vth, *Vtl;
    __nv_bfloat16 *Wqth, *Wqtl, *Wkth, *Wktl, *Wvth, *Wvtl, *Ph, *Pl;
    float* S;
    cudaGetSymbolAddress((void**)&Xh, g_Xh);   cudaGetSymbolAddress((void**)&Xl, g_Xl);
    cudaGetSymbolAddress((void**)&Qh, g_Qh);   cudaGetSymbolAddress((void**)&Ql, g_Ql);
    cudaGetSymbolAddress((void**)&Kh, g_Kh);   cudaGetSymbolAddress((void**)&Kl, g_Kl);
    cudaGetSymbolAddress((void**)&Vth, g_Vth); cudaGetSymbolAddress((void**)&Vtl, g_Vtl);
    cudaGetSymbolAddress((void**)&Wqth, g_Wqth); cudaGetSymbolAddress((void**)&Wqtl, g_Wqtl);
    cudaGetSymbolAddress((void**)&Wkth, g_Wkth); cudaGetSymbolAddress((void**)&Wktl, g_Wktl);
    cudaGetSymbolAddress((void**)&Wvth, g_Wvth); cudaGetSymbolAddress((void**)&Wvtl, g_Wvtl);
    cudaGetSymbolAddress((void**)&Ph, g_Ph);   cudaGetSymbolAddress((void**)&Pl, g_Pl);
    cudaGetSymbolAddress((void**)&S, g_S);

    cudaFuncSetAttribute((const void*)tc_gemm<1, 1>, cudaFuncAttributeMaxDynamicSharedMemorySize, (int)SMEM_BYTES);
    cudaFuncSetAttribute((const void*)tc_gemm<1, 2>, cudaFuncAttributeMaxDynamicSharedMemorySize, (int)SMEM_BYTES);
    cudaFuncSetAttribute((const void*)tc_gemm<0, 0>, cudaFuncAttributeMaxDynamicSharedMemorySize, (int)SMEM_BYTES);

    dim3 blk(256);

    // 0) split X, transpose+split weights
    split_x_kernel<<<(MTOT * D_) / 1024, 256>>>(X, Xh, Xl);
    transpose_split_kernel<<<dim3(32, 32, 3), dim3(32, 8)>>>(
        Wq, Wk, Wv, Wqth, Wqtl, Wkth, Wktl, Wvth, Wvtl);

    // 1) Q = X Wq^T + bq ; K = X Wk^T + bk   (split-bf16 outputs)
    tc_gemm<1, 1><<<dim3(8, 64, 1), blk, SMEM_BYTES>>>(
        Xh, Xl, D_, 0, Wqth, Wqtl, D_, 0, nullptr, Qh, Ql, D_, 0, bq, D_);
    tc_gemm<1, 1><<<dim3(8, 64, 1), blk, SMEM_BYTES>>>(
        Xh, Xl, D_, 0, Wkth, Wktl, D_, 0, nullptr, Kh, Kl, D_, 0, bk, D_);
    // 1b) V^T[e,m] = Wv^T X^T + bv (bias by row e)
    tc_gemm<1, 2><<<dim3(64, 8, 1), blk, SMEM_BYTES>>>(
        Wvth, Wvtl, D_, 0, Xh, Xl, D_, 0, nullptr, Vth, Vtl, MTOT, 0, bv, D_);

    // 2) S = Q K^T per batch (fp32)
    tc_gemm<0, 0><<<dim3(16, 16, B_), blk, SMEM_BYTES>>>(
        Qh, Ql, D_, (long)N_ * D_, Kh, Kl, D_, (long)N_ * D_,
        S, nullptr, nullptr, N_, (long)N_ * N_, nullptr, D_);

    // 3) softmax + split P
    softmax_split_kernel<<<B_ * N_, 256>>>(S, Ph, Pl);

    // 4) out = P V per batch (NT against V^T, fp32 out)
    tc_gemm<0, 0><<<dim3(8, 16, B_), blk, SMEM_BYTES>>>(
        Ph, Pl, N_, (long)N_ * N_, Vth, Vtl, MTOT, (long)N_,
        out, nullptr, nullptr, D_, (long)N_ * D_, nullptr, N_);
}

// round 6
// speedup vs baseline: 2.2157x; 1.5397x over previous
#include <cuda_runtime.h>
#include <cuda_bf16.h>
#include <cstdint>
#include <math.h>

// Problem constants
constexpr int B_   = 4;
constexpr int N_   = 2048;
constexpr int D_   = 1024;
constexpr int MTOT = B_ * N_;  // 8192

// ---------------- scratch (static __device__, allocation-free) ----------------
__device__ __align__(1024) __nv_bfloat16 g_Xh[(size_t)MTOT * D_];
__device__ __align__(1024) __nv_bfloat16 g_Xl[(size_t)MTOT * D_];
__device__ __align__(1024) __nv_bfloat16 g_Qh[(size_t)MTOT * D_];
__device__ __align__(1024) __nv_bfloat16 g_Ql[(size_t)MTOT * D_];
__device__ __align__(1024) __nv_bfloat16 g_Kh[(size_t)MTOT * D_];
__device__ __align__(1024) __nv_bfloat16 g_Kl[(size_t)MTOT * D_];
__device__ __align__(1024) __nv_bfloat16 g_Vth[(size_t)D_ * MTOT];   // V^T [e][m]
__device__ __align__(1024) __nv_bfloat16 g_Vtl[(size_t)D_ * MTOT];
__device__ __align__(1024) __nv_bfloat16 g_Wqth[(size_t)D_ * D_];    // W^T [e][d]
__device__ __align__(1024) __nv_bfloat16 g_Wqtl[(size_t)D_ * D_];
__device__ __align__(1024) __nv_bfloat16 g_Wkth[(size_t)D_ * D_];
__device__ __align__(1024) __nv_bfloat16 g_Wktl[(size_t)D_ * D_];
__device__ __align__(1024) __nv_bfloat16 g_Wvth[(size_t)D_ * D_];
__device__ __align__(1024) __nv_bfloat16 g_Wvtl[(size_t)D_ * D_];
__device__ __align__(1024) float         g_S [(size_t)B_ * N_ * N_]; // 64 MB
__device__ __align__(1024) __nv_bfloat16 g_Ph[(size_t)B_ * N_ * N_];
__device__ __align__(1024) __nv_bfloat16 g_Pl[(size_t)B_ * N_ * N_];

// ---------------- helpers (plain sm_80-level PTX only; no 'a' features) -------
__device__ __forceinline__ uint32_t s2u(const void* p) {
    uint32_t a;
    asm("{ .reg .u64 t; cvta.to.shared.u64 t, %1; cvt.u32.u64 %0, t; }" : "=r"(a) : "l"(p));
    return a;
}
__device__ __forceinline__ void cpasync16(uint32_t dst, const void* src) {
    asm volatile("cp.async.cg.shared.global [%0], [%1], 16;" :: "r"(dst), "l"(src));
}
__device__ __forceinline__ void ldm4(uint32_t (&r)[4], uint32_t addr) {
    asm volatile("ldmatrix.sync.aligned.m8n8.x4.shared.b16 {%0,%1,%2,%3}, [%4];"
                 : "=r"(r[0]), "=r"(r[1]), "=r"(r[2]), "=r"(r[3]) : "r"(addr));
}
__device__ __forceinline__ void mma16816(float (&c)[4], const uint32_t* a,
                                         uint32_t b0, uint32_t b1) {
    asm volatile(
        "mma.sync.aligned.m16n8k16.row.col.f32.bf16.bf16.f32 "
        "{%0,%1,%2,%3}, {%4,%5,%6,%7}, {%8,%9}, {%0,%1,%2,%3};"
        : "+f"(c[0]), "+f"(c[1]), "+f"(c[2]), "+f"(c[3])
        : "r"(a[0]), "r"(a[1]), "r"(a[2]), "r"(a[3]), "r"(b0), "r"(b1));
}
// Tile row = 32 bf16 = 64B; swizzle 16B chunk index within row for conflict-free ldmatrix
__device__ __forceinline__ uint32_t swoff(int row, int kb) {
    return (uint32_t)(row * 64 + ((kb ^ ((row >> 1) & 3)) << 4));
}

constexpr int TILE_BYTES = 128 * 32 * 2;     // 8 KB: 128 rows x 32 bf16
constexpr int STAGES     = 4;
constexpr size_t SMEM_BYTES = (size_t)STAGES * 4 * TILE_BYTES;  // 128 KB

// ================= split-bf16 mma.sync GEMM =================
// C[m0+m, n0+n] = sum_k (Ah+Al)[m,k] * (Bh+Bl)[n,k]   (NT, both K-major)
// OUTMODE: 0 = fp32 C, 1 = split hi/lo bf16 C. BIASMODE: 0 none, 1 by col, 2 by row.
template<int OUTMODE, int BIASMODE>
__global__ void __launch_bounds__(256, 1)
tc_gemm(const __nv_bfloat16* __restrict__ Ah, const __nv_bfloat16* __restrict__ Al,
        int lda, long sA,
        const __nv_bfloat16* __restrict__ Bh, const __nv_bfloat16* __restrict__ Bl,
        int ldb, long sB,
        float* __restrict__ Cf, __nv_bfloat16* __restrict__ Ch, __nv_bfloat16* __restrict__ Cl,
        int ldc, long sC, const float* __restrict__ bias, int Kd)
{
    extern __shared__ __align__(128) char dsm[];
    const uint32_t base = s2u(dsm);

    const int tid = threadIdx.x, wid = tid >> 5, lid = tid & 31;
    const int wm = wid >> 2, wn = wid & 3;       // warp grid 2 x 4, warp tile 64x32
    const int m0 = blockIdx.y * 128, n0 = blockIdx.x * 128;
    const long z = blockIdx.z;
    Ah += z * sA; Al += z * sA; Bh += z * sB; Bl += z * sB;

    const __nv_bfloat16* srcs[4] = {
        Ah + (long)m0 * lda, Al + (long)m0 * lda,
        Bh + (long)n0 * ldb, Bl + (long)n0 * ldb };
    const int ldsv[4] = { lda, lda, ldb, ldb };

    auto load_chunk = [&](int chunk, int stage) {
        #pragma unroll
        for (int p = 0; p < 4; p++) {
            const __nv_bfloat16* s = srcs[p] + chunk * 32;
            const int ld = ldsv[p];
            const uint32_t tb = base + (uint32_t)((stage * 4 + p) * TILE_BYTES);
            #pragma unroll
            for (int i = 0; i < 2; i++) {
                int o = i * 256 + tid;          // 512 chunks of 16B
                int r = o >> 2, kb = o & 3;
                cpasync16(tb + swoff(r, kb), s + (long)r * ld + kb * 8);
            }
        }
        asm volatile("cp.async.commit_group;" ::: "memory");
    };

    float acc[4][4][4];
    #pragma unroll
    for (int i = 0; i < 4; i++)
        #pragma unroll
        for (int t = 0; t < 4; t++)
            #pragma unroll
            for (int j = 0; j < 4; j++) acc[i][t][j] = 0.0f;

    const int nk = Kd / 32;
    load_chunk(0, 0); load_chunk(1, 1); load_chunk(2, 2);

    const int rA  = (lid & 7) + ((lid >> 3) & 1) * 8;  // ldmatrix row-in-16
    const int kbh = (lid >> 4) & 1;                    // ldmatrix k-half

    for (int k = 0; k < nk; k++) {
        if (k + 3 <= nk)      asm volatile("cp.async.wait_group 2;" ::: "memory");
        else if (k + 2 == nk) asm volatile("cp.async.wait_group 1;" ::: "memory");
        else                  asm volatile("cp.async.wait_group 0;" ::: "memory");
        __syncthreads();
        // The barrier above also guarantees every warp finished computing
        // chunk k-1, so its stage ((k+3)%STAGES with STAGES=4) is free now:
        // issue the next load FIRST, then compute — no trailing barrier needed.
        if (k + 3 < nk) load_chunk(k + 3, (k + 3) % STAGES);

        const int stage = k % STAGES;
        const uint32_t tAh = base + (uint32_t)((stage * 4 + 0) * TILE_BYTES);
        const uint32_t tAl = base + (uint32_t)((stage * 4 + 1) * TILE_BYTES);
        const uint32_t tBh = base + (uint32_t)((stage * 4 + 2) * TILE_BYTES);
        const uint32_t tBl = base + (uint32_t)((stage * 4 + 3) * TILE_BYTES);

        #pragma unroll
        for (int p = 0; p < 2; p++) {            // two k16 steps per 32-chunk
            const int kb = 2 * p + kbh;
            uint32_t fAh[4][4], fAl[4][4], fBh[2][4], fBl[2][4];
            #pragma unroll
            for (int i = 0; i < 4; i++) {
                const uint32_t o = swoff(wm * 64 + i * 16 + rA, kb);
                ldm4(fAh[i], tAh + o);
                ldm4(fAl[i], tAl + o);
            }
            #pragma unroll
            for (int q = 0; q < 2; q++) {
                const uint32_t o = swoff(wn * 32 + q * 16 + rA, kb);
                ldm4(fBh[q], tBh + o);
                ldm4(fBl[q], tBl + o);
            }
            // Three passes over all 16 accumulator tiles: the RAW distance on
            // each acc[i][nt] is 16 MMAs, so the HMMA pipe never stalls on a
            // dependent accumulate (was: 3 chained MMAs back-to-back).
            #pragma unroll
            for (int i = 0; i < 4; i++)
                #pragma unroll
                for (int nt = 0; nt < 4; nt++) {
                    const int q = nt >> 1, sx = nt & 1;
                    mma16816(acc[i][nt], fAh[i], fBh[q][sx], fBh[q][sx + 2]);
                }
            #pragma unroll
            for (int i = 0; i < 4; i++)
                #pragma unroll
                for (int nt = 0; nt < 4; nt++) {
                    const int q = nt >> 1, sx = nt & 1;
                    mma16816(acc[i][nt], fAh[i], fBl[q][sx], fBl[q][sx + 2]);
                }
            #pragma unroll
            for (int i = 0; i < 4; i++)
                #pragma unroll
                for (int nt = 0; nt < 4; nt++) {
                    const int q = nt >> 1, sx = nt & 1;
                    mma16816(acc[i][nt], fAl[i], fBh[q][sx], fBh[q][sx + 2]);
                }
        }
    }

    // ---------------- epilogue: direct register -> gmem ----------------
    #pragma unroll
    for (int i = 0; i < 4; i++)
        #pragma unroll
        for (int nt = 0; nt < 4; nt++) {
            const int row = m0 + wm * 64 + i * 16 + (lid >> 2);
            const int col = n0 + wn * 32 + nt * 8 + 2 * (lid & 3);
            float v0 = acc[i][nt][0], v1 = acc[i][nt][1];
            float v2 = acc[i][nt][2], v3 = acc[i][nt][3];
            if (BIASMODE == 1) {
                const float b0 = bias[col], b1 = bias[col + 1];
                v0 += b0; v1 += b1; v2 += b0; v3 += b1;
            } else if (BIASMODE == 2) {
                const float b0 = bias[row], b1 = bias[row + 8];
                v0 += b0; v1 += b0; v2 += b1; v3 += b1;
            }
            const long o0 = (long)row * ldc + col + z * sC;
            const long o1 = o0 + 8L * ldc;
            if (OUTMODE == 0) {
                *(float2*)(Cf + o0) = make_float2(v0, v1);
                *(float2*)(Cf + o1) = make_float2(v2, v3);
            } else {
                __nv_bfloat16 h0 = __float2bfloat16(v0), h1 = __float2bfloat16(v1);
                __nv_bfloat16 h2 = __float2bfloat16(v2), h3 = __float2bfloat16(v3);
                __nv_bfloat16 l0 = __float2bfloat16(v0 - __bfloat162float(h0));
                __nv_bfloat16 l1 = __float2bfloat16(v1 - __bfloat162float(h1));
                __nv_bfloat16 l2 = __float2bfloat16(v2 - __bfloat162float(h2));
                __nv_bfloat16 l3 = __float2bfloat16(v3 - __bfloat162float(h3));
                __nv_bfloat162 ph0; ph0.x = h0; ph0.y = h1;
                __nv_bfloat162 ph1; ph1.x = h2; ph1.y = h3;
                __nv_bfloat162 pl0; pl0.x = l0; pl0.y = l1;
                __nv_bfloat162 pl1; pl1.x = l2; pl1.y = l3;
                *(__nv_bfloat162*)(Ch + o0) = ph0;
                *(__nv_bfloat162*)(Ch + o1) = ph1;
                *(__nv_bfloat162*)(Cl + o0) = pl0;
                *(__nv_bfloat162*)(Cl + o1) = pl1;
            }
        }
}

// ================= prep kernels =================
__global__ void __launch_bounds__(256)
split_x_kernel(const float* __restrict__ X, __nv_bfloat16* __restrict__ Xh,
               __nv_bfloat16* __restrict__ Xl)
{
    const long i = ((long)blockIdx.x * 256 + threadIdx.x) * 4;
    float4 v = *(const float4*)(X + i);
    float vv[4] = { v.x, v.y, v.z, v.w };
    __nv_bfloat16 h[4], l[4];
    #pragma unroll
    for (int j = 0; j < 4; j++) {
        h[j] = __float2bfloat16(vv[j]);
        l[j] = __float2bfloat16(vv[j] - __bfloat162float(h[j]));
    }
    __nv_bfloat162 h01, h23, l01, l23;
    h01.x = h[0]; h01.y = h[1]; h23.x = h[2]; h23.y = h[3];
    l01.x = l[0]; l01.y = l[1]; l23.x = l[2]; l23.y = l[3];
    *(__nv_bfloat162*)(Xh + i)     = h01;
    *(__nv_bfloat162*)(Xh + i + 2) = h23;
    *(__nv_bfloat162*)(Xl + i)     = l01;
    *(__nv_bfloat162*)(Xl + i + 2) = l23;
}

// Transpose + split 1024x1024 weights: T[e][d] = W[d][e]
__global__ void __launch_bounds__(256)
transpose_split_kernel(const float* __restrict__ W0, const float* __restrict__ W1,
                       const float* __restrict__ W2,
                       __nv_bfloat16* __restrict__ T0h, __nv_bfloat16* __restrict__ T0l,
                       __nv_bfloat16* __restrict__ T1h, __nv_bfloat16* __restrict__ T1l,
                       __nv_bfloat16* __restrict__ T2h, __nv_bfloat16* __restrict__ T2l)
{
    __shared__ float t[32][33];
    const float* W = (blockIdx.z == 0) ? W0 : (blockIdx.z == 1) ? W1 : W2;
    __nv_bfloat16* Th = (blockIdx.z == 0) ? T0h : (blockIdx.z == 1) ? T1h : T2h;
    __nv_bfloat16* Tl = (blockIdx.z == 0) ? T0l : (blockIdx.z == 1) ? T1l : T2l;

    const int tx = threadIdx.x, ty = threadIdx.y;       // block 32x8
    const int e = blockIdx.x * 32 + tx;
    const int d0 = blockIdx.y * 32;
    #pragma unroll
    for (int i = ty; i < 32; i += 8)
        t[i][tx] = W[(long)(d0 + i) * D_ + e];
    __syncthreads();
    const int eo = blockIdx.x * 32;
    const int d = d0 + tx;
    #pragma unroll
    for (int i = ty; i < 32; i += 8) {
        float w = t[tx][i];
        __nv_bfloat16 h = __float2bfloat16(w);
        __nv_bfloat16 l = __float2bfloat16(w - __bfloat162float(h));
        Th[(long)(eo + i) * D_ + d] = h;
        Tl[(long)(eo + i) * D_ + d] = l;
    }
}

// Row softmax over S (length 2048), write split-bf16 P.
__global__ void __launch_bounds__(256)
softmax_split_kernel(const float* __restrict__ S, __nv_bfloat16* __restrict__ Ph,
                     __nv_bfloat16* __restrict__ Pl)
{
    const long row = blockIdx.x;
    const float* p = S + row * (long)N_;
    const int tid = threadIdx.x;

    float v[8];
    float mx = -1e30f;
    #pragma unroll
    for (int i = 0; i < 8; i++) { v[i] = p[tid + i * 256]; mx = fmaxf(mx, v[i]); }

    __shared__ float redm[8], reds[8];
    #pragma unroll
    for (int o = 16; o; o >>= 1) mx = fmaxf(mx, __shfl_xor_sync(0xffffffffu, mx, o));
    if ((tid & 31) == 0) redm[tid >> 5] = mx;
    __syncthreads();
    if (tid == 0) {
        float m = redm[0];
        #pragma unroll
        for (int i = 1; i < 8; i++) m = fmaxf(m, redm[i]);
        redm[0] = m;
    }
    __syncthreads();
    mx = redm[0];

    float s = 0.0f;
    #pragma unroll
    for (int i = 0; i < 8; i++) { v[i] = __expf(v[i] - mx); s += v[i]; }
    #pragma unroll
    for (int o = 16; o; o >>= 1) s += __shfl_xor_sync(0xffffffffu, s, o);
    if ((tid & 31) == 0) reds[tid >> 5] = s;
    __syncthreads();
    if (tid == 0) {
        float m = 0.0f;
        #pragma unroll
        for (int i = 0; i < 8; i++) m += reds[i];
        reds[0] = m;
    }
    __syncthreads();
    const float inv = 1.0f / reds[0];

    #pragma unroll
    for (int i = 0; i < 8; i++) {
        float w = v[i] * inv;
        __nv_bfloat16 h = __float2bfloat16(w);
        __nv_bfloat16 l = __float2bfloat16(w - __bfloat162float(h));
        Ph[row * (long)N_ + tid + i * 256] = h;
        Pl[row * (long)N_ + tid + i * 256] = l;
    }
}

// ================= host glue =================
extern "C" void kernel_launch(void* const* d_in, const int* in_sizes, int n_in,
                              void* d_out, int out_size)
{
    const float* X  = (const float*)d_in[0];
    const float* Wq = (const float*)d_in[1];
    const float* bq = (const float*)d_in[2];
    const float* Wk = (const float*)d_in[3];
    const float* bk = (const float*)d_in[4];
    const float* Wv = (const float*)d_in[5];
    const float* bv = (const float*)d_in[6];
    float* out = (float*)d_out;

    __nv_bfloat16 *Xh, *Xl, *Qh, *Ql, *Kh, *Kl, *Vth, *Vtl;
    __nv_bfloat16 *Wqth, *Wqtl, *Wkth, *Wktl, *Wvth, *Wvtl, *Ph, *Pl;
    float* S;
    cudaGetSymbolAddress((void**)&Xh, g_Xh);   cudaGetSymbolAddress((void**)&Xl, g_Xl);
    cudaGetSymbolAddress((void**)&Qh, g_Qh);   cudaGetSymbolAddress((void**)&Ql, g_Ql);
    cudaGetSymbolAddress((void**)&Kh, g_Kh);   cudaGetSymbolAddress((void**)&Kl, g_Kl);
    cudaGetSymbolAddress((void**)&Vth, g_Vth); cudaGetSymbolAddress((void**)&Vtl, g_Vtl);
    cudaGetSymbolAddress((void**)&Wqth, g_Wqth); cudaGetSymbolAddress((void**)&Wqtl, g_Wqtl);
    cudaGetSymbolAddress((void**)&Wkth, g_Wkth); cudaGetSymbolAddress((void**)&Wktl, g_Wktl);
    cudaGetSymbolAddress((void**)&Wvth, g_Wvth); cudaGetSymbolAddress((void**)&Wvtl, g_Wvtl);
    cudaGetSymbolAddress((void**)&Ph, g_Ph);   cudaGetSymbolAddress((void**)&Pl, g_Pl);
    cudaGetSymbolAddress((void**)&S, g_S);

    cudaFuncSetAttribute((const void*)tc_gemm<1, 1>, cudaFuncAttributeMaxDynamicSharedMemorySize, (int)SMEM_BYTES);
    cudaFuncSetAttribute((const void*)tc_gemm<1, 2>, cudaFuncAttributeMaxDynamicSharedMemorySize, (int)SMEM_BYTES);
    cudaFuncSetAttribute((const void*)tc_gemm<0, 0>, cudaFuncAttributeMaxDynamicSharedMemorySize, (int)SMEM_BYTES);

    dim3 blk(256);

    // 0) split X, transpose+split weights
    split_x_kernel<<<(MTOT * D_) / 1024, 256>>>(X, Xh, Xl);
    transpose_split_kernel<<<dim3(32, 32, 3), dim3(32, 8)>>>(
        Wq, Wk, Wv, Wqth, Wqtl, Wkth, Wktl, Wvth, Wvtl);

    // 1) Q = X Wq^T + bq ; K = X Wk^T + bk   (split-bf16 outputs)
    tc_gemm<1, 1><<<dim3(8, 64, 1), blk, SMEM_BYTES>>>(
        Xh, Xl, D_, 0, Wqth, Wqtl, D_, 0, nullptr, Qh, Ql, D_, 0, bq, D_);
    tc_gemm<1, 1><<<dim3(8, 64, 1), blk, SMEM_BYTES>>>(
        Xh, Xl, D_, 0, Wkth, Wktl, D_, 0, nullptr, Kh, Kl, D_, 0, bk, D_);
    // 1b) V^T[e,m] = Wv^T X^T + bv (bias by row e)
    tc_gemm<1, 2><<<dim3(64, 8, 1), blk, SMEM_BYTES>>>(
        Wvth, Wvtl, D_, 0, Xh, Xl, D_, 0, nullptr, Vth, Vtl, MTOT, 0, bv, D_);

    // 2) S = Q K^T per batch (fp32)
    tc_gemm<0, 0><<<dim3(16, 16, B_), blk, SMEM_BYTES>>>(
        Qh, Ql, D_, (long)N_ * D_, Kh, Kl, D_, (long)N_ * D_,
        S, nullptr, nullptr, N_, (long)N_ * N_, nullptr, D_);

    // 3) softmax + split P
    softmax_split_kernel<<<B_ * N_, 256>>>(S, Ph, Pl);

    // 4) out = P V per batch (NT against V^T, fp32 out)
    tc_gemm<0, 0><<<dim3(8, 16, B_), blk, SMEM_BYTES>>>(
        Ph, Pl, N_, (long)N_ * N_, Vth, Vtl, MTOT, (long)N_,
        out, nullptr, nullptr, D_, (long)N_ * D_, nullptr, N_);
}

// round 7
// speedup vs baseline: 2.4962x; 1.1266x over previous
#include <cuda_runtime.h>
#include <cuda_bf16.h>
#include <cstdint>
#include <math.h>

// Problem constants
constexpr int B_   = 4;
constexpr int N_   = 2048;
constexpr int D_   = 1024;
constexpr int MTOT = B_ * N_;  // 8192

// ---------------- scratch (static __device__, allocation-free) ----------------
__device__ __align__(1024) __nv_bfloat16 g_Xh[(size_t)MTOT * D_];
__device__ __align__(1024) __nv_bfloat16 g_Xl[(size_t)MTOT * D_];
__device__ __align__(1024) __nv_bfloat16 g_Qh[(size_t)MTOT * D_];
__device__ __align__(1024) __nv_bfloat16 g_Ql[(size_t)MTOT * D_];
__device__ __align__(1024) __nv_bfloat16 g_Kh[(size_t)MTOT * D_];
__device__ __align__(1024) __nv_bfloat16 g_Kl[(size_t)MTOT * D_];
__device__ __align__(1024) __nv_bfloat16 g_Vth[(size_t)D_ * MTOT];   // V^T [e][m]
__device__ __align__(1024) __nv_bfloat16 g_Vtl[(size_t)D_ * MTOT];
__device__ __align__(1024) __nv_bfloat16 g_Wqth[(size_t)D_ * D_];    // W^T [e][d]
__device__ __align__(1024) __nv_bfloat16 g_Wqtl[(size_t)D_ * D_];
__device__ __align__(1024) __nv_bfloat16 g_Wkth[(size_t)D_ * D_];
__device__ __align__(1024) __nv_bfloat16 g_Wktl[(size_t)D_ * D_];
__device__ __align__(1024) __nv_bfloat16 g_Wvth[(size_t)D_ * D_];
__device__ __align__(1024) __nv_bfloat16 g_Wvtl[(size_t)D_ * D_];
__device__ __align__(1024) float         g_S [(size_t)B_ * N_ * N_]; // 64 MB
__device__ __align__(1024) __nv_bfloat16 g_Ph[(size_t)B_ * N_ * N_];
__device__ __align__(1024) __nv_bfloat16 g_Pl[(size_t)B_ * N_ * N_];

// ---------------- helpers (plain sm_80-level PTX only; no 'a' features) -------
__device__ __forceinline__ uint32_t s2u(const void* p) {
    uint32_t a;
    asm("{ .reg .u64 t; cvta.to.shared.u64 t, %1; cvt.u32.u64 %0, t; }" : "=r"(a) : "l"(p));
    return a;
}
__device__ __forceinline__ void cpasync16(uint32_t dst, const void* src) {
    asm volatile("cp.async.cg.shared.global [%0], [%1], 16;" :: "r"(dst), "l"(src));
}
__device__ __forceinline__ void ldm4(uint32_t (&r)[4], uint32_t addr) {
    asm volatile("ldmatrix.sync.aligned.m8n8.x4.shared.b16 {%0,%1,%2,%3}, [%4];"
                 : "=r"(r[0]), "=r"(r[1]), "=r"(r[2]), "=r"(r[3]) : "r"(addr));
}
__device__ __forceinline__ void mma16816(float (&c)[4], const uint32_t* a,
                                         uint32_t b0, uint32_t b1) {
    asm volatile(
        "mma.sync.aligned.m16n8k16.row.col.f32.bf16.bf16.f32 "
        "{%0,%1,%2,%3}, {%4,%5,%6,%7}, {%8,%9}, {%0,%1,%2,%3};"
        : "+f"(c[0]), "+f"(c[1]), "+f"(c[2]), "+f"(c[3])
        : "r"(a[0]), "r"(a[1]), "r"(a[2]), "r"(a[3]), "r"(b0), "r"(b1));
}
// Tile row = 32 bf16 = 64B; swizzle 16B chunk index within row for conflict-free ldmatrix
__device__ __forceinline__ uint32_t swoff(int row, int kb) {
    return (uint32_t)(row * 64 + ((kb ^ ((row >> 1) & 3)) << 4));
}

constexpr int TILE_BYTES = 128 * 32 * 2;     // 8 KB: 128 rows x 32 bf16
constexpr int STAGES     = 3;
constexpr size_t SMEM_BYTES = (size_t)STAGES * 4 * TILE_BYTES;  // 96 KB -> 2 CTAs/SM

// ================= split-bf16 mma.sync GEMM =================
// C[m0+m, n0+n] = sum_k (Ah+Al)[m,k] * (Bh+Bl)[n,k]   (NT, both K-major)
// OUTMODE: 0 = fp32 C, 1 = split hi/lo bf16 C. BIASMODE: 0 none, 1 by col, 2 by row.
template<int OUTMODE, int BIASMODE>
__global__ void __launch_bounds__(256, 2)
tc_gemm(const __nv_bfloat16* __restrict__ Ah, const __nv_bfloat16* __restrict__ Al,
        int lda, long sA,
        const __nv_bfloat16* __restrict__ Bh, const __nv_bfloat16* __restrict__ Bl,
        int ldb, long sB,
        float* __restrict__ Cf, __nv_bfloat16* __restrict__ Ch, __nv_bfloat16* __restrict__ Cl,
        int ldc, long sC, const float* __restrict__ bias, int Kd)
{
    extern __shared__ __align__(128) char dsm[];
    const uint32_t base = s2u(dsm);

    const int tid = threadIdx.x, wid = tid >> 5, lid = tid & 31;
    const int wm = wid >> 2, wn = wid & 3;       // warp grid 2 x 4, warp tile 64x32
    const int m0 = blockIdx.y * 128, n0 = blockIdx.x * 128;
    const long z = blockIdx.z;
    Ah += z * sA; Al += z * sA; Bh += z * sB; Bl += z * sB;

    const __nv_bfloat16* srcs[4] = {
        Ah + (long)m0 * lda, Al + (long)m0 * lda,
        Bh + (long)n0 * ldb, Bl + (long)n0 * ldb };
    const int ldsv[4] = { lda, lda, ldb, ldb };

    auto load_chunk = [&](int chunk, int stage) {
        #pragma unroll
        for (int p = 0; p < 4; p++) {
            const __nv_bfloat16* s = srcs[p] + chunk * 32;
            const int ld = ldsv[p];
            const uint32_t tb = base + (uint32_t)((stage * 4 + p) * TILE_BYTES);
            #pragma unroll
            for (int i = 0; i < 2; i++) {
                int o = i * 256 + tid;          // 512 chunks of 16B
                int r = o >> 2, kb = o & 3;
                cpasync16(tb + swoff(r, kb), s + (long)r * ld + kb * 8);
            }
        }
        asm volatile("cp.async.commit_group;" ::: "memory");
    };

    float acc[4][4][4];
    #pragma unroll
    for (int i = 0; i < 4; i++)
        #pragma unroll
        for (int t = 0; t < 4; t++)
            #pragma unroll
            for (int j = 0; j < 4; j++) acc[i][t][j] = 0.0f;

    const int nk = Kd / 32;
    load_chunk(0, 0); load_chunk(1, 1); load_chunk(2, 2);

    const int rA  = (lid & 7) + ((lid >> 3) & 1) * 8;  // ldmatrix row-in-16
    const int kbh = (lid >> 4) & 1;                    // ldmatrix k-half

    for (int k = 0; k < nk; k++) {
        if (k + 3 <= nk)      asm volatile("cp.async.wait_group 2;" ::: "memory");
        else if (k + 2 == nk) asm volatile("cp.async.wait_group 1;" ::: "memory");
        else                  asm volatile("cp.async.wait_group 0;" ::: "memory");
        __syncthreads();

        const int stage = k % STAGES;
        const uint32_t tAh = base + (uint32_t)((stage * 4 + 0) * TILE_BYTES);
        const uint32_t tAl = base + (uint32_t)((stage * 4 + 1) * TILE_BYTES);
        const uint32_t tBh = base + (uint32_t)((stage * 4 + 2) * TILE_BYTES);
        const uint32_t tBl = base + (uint32_t)((stage * 4 + 3) * TILE_BYTES);

        #pragma unroll
        for (int p = 0; p < 2; p++) {            // two k16 steps per 32-chunk
            const int kb = 2 * p + kbh;
            uint32_t fAh[4][4], fAl[4][4], fBh[2][4], fBl[2][4];
            #pragma unroll
            for (int i = 0; i < 4; i++) {
                const uint32_t o = swoff(wm * 64 + i * 16 + rA, kb);
                ldm4(fAh[i], tAh + o);
                ldm4(fAl[i], tAl + o);
            }
            #pragma unroll
            for (int q = 0; q < 2; q++) {
                const uint32_t o = swoff(wn * 32 + q * 16 + rA, kb);
                ldm4(fBh[q], tBh + o);
                ldm4(fBl[q], tBl + o);
            }
            // Three passes over all 16 accumulator tiles: RAW distance 16 MMAs.
            #pragma unroll
            for (int i = 0; i < 4; i++)
                #pragma unroll
                for (int nt = 0; nt < 4; nt++) {
                    const int q = nt >> 1, sx = nt & 1;
                    mma16816(acc[i][nt], fAh[i], fBh[q][sx], fBh[q][sx + 2]);
                }
            #pragma unroll
            for (int i = 0; i < 4; i++)
                #pragma unroll
                for (int nt = 0; nt < 4; nt++) {
                    const int q = nt >> 1, sx = nt & 1;
                    mma16816(acc[i][nt], fAh[i], fBl[q][sx], fBl[q][sx + 2]);
                }
            #pragma unroll
            for (int i = 0; i < 4; i++)
                #pragma unroll
                for (int nt = 0; nt < 4; nt++) {
                    const int q = nt >> 1, sx = nt & 1;
                    mma16816(acc[i][nt], fAl[i], fBh[q][sx], fBh[q][sx + 2]);
                }
        }
        // 3-stage ring: stage of chunk k is reused by chunk k+3, so all warps
        // must finish computing before the next load — trailing barrier. Its
        // bubble is hidden by the co-resident CTA (2 CTAs/SM).
        __syncthreads();
        if (k + 3 < nk) load_chunk(k + 3, stage);
    }

    // ---------------- epilogue: direct register -> gmem ----------------
    #pragma unroll
    for (int i = 0; i < 4; i++)
        #pragma unroll
        for (int nt = 0; nt < 4; nt++) {
            const int row = m0 + wm * 64 + i * 16 + (lid >> 2);
            const int col = n0 + wn * 32 + nt * 8 + 2 * (lid & 3);
            float v0 = acc[i][nt][0], v1 = acc[i][nt][1];
            float v2 = acc[i][nt][2], v3 = acc[i][nt][3];
            if (BIASMODE == 1) {
                const float b0 = bias[col], b1 = bias[col + 1];
                v0 += b0; v1 += b1; v2 += b0; v3 += b1;
            } else if (BIASMODE == 2) {
                const float b0 = bias[row], b1 = bias[row + 8];
                v0 += b0; v1 += b0; v2 += b1; v3 += b1;
            }
            const long o0 = (long)row * ldc + col + z * sC;
            const long o1 = o0 + 8L * ldc;
            if (OUTMODE == 0) {
                *(float2*)(Cf + o0) = make_float2(v0, v1);
                *(float2*)(Cf + o1) = make_float2(v2, v3);
            } else {
                __nv_bfloat16 h0 = __float2bfloat16(v0), h1 = __float2bfloat16(v1);
                __nv_bfloat16 h2 = __float2bfloat16(v2), h3 = __float2bfloat16(v3);
                __nv_bfloat16 l0 = __float2bfloat16(v0 - __bfloat162float(h0));
                __nv_bfloat16 l1 = __float2bfloat16(v1 - __bfloat162float(h1));
                __nv_bfloat16 l2 = __float2bfloat16(v2 - __bfloat162float(h2));
                __nv_bfloat16 l3 = __float2bfloat16(v3 - __bfloat162float(h3));
                __nv_bfloat162 ph0; ph0.x = h0; ph0.y = h1;
                __nv_bfloat162 ph1; ph1.x = h2; ph1.y = h3;
                __nv_bfloat162 pl0; pl0.x = l0; pl0.y = l1;
                __nv_bfloat162 pl1; pl1.x = l2; pl1.y = l3;
                *(__nv_bfloat162*)(Ch + o0) = ph0;
                *(__nv_bfloat162*)(Ch + o1) = ph1;
                *(__nv_bfloat162*)(Cl + o0) = pl0;
                *(__nv_bfloat162*)(Cl + o1) = pl1;
            }
        }
}

// ================= prep kernels =================
__global__ void __launch_bounds__(256)
split_x_kernel(const float* __restrict__ X, __nv_bfloat16* __restrict__ Xh,
               __nv_bfloat16* __restrict__ Xl)
{
    const long i = ((long)blockIdx.x * 256 + threadIdx.x) * 4;
    float4 v = *(const float4*)(X + i);
    float vv[4] = { v.x, v.y, v.z, v.w };
    __nv_bfloat16 h[4], l[4];
    #pragma unroll
    for (int j = 0; j < 4; j++) {
        h[j] = __float2bfloat16(vv[j]);
        l[j] = __float2bfloat16(vv[j] - __bfloat162float(h[j]));
    }
    __nv_bfloat162 h01, h23, l01, l23;
    h01.x = h[0]; h01.y = h[1]; h23.x = h[2]; h23.y = h[3];
    l01.x = l[0]; l01.y = l[1]; l23.x = l[2]; l23.y = l[3];
    *(__nv_bfloat162*)(Xh + i)     = h01;
    *(__nv_bfloat162*)(Xh + i + 2) = h23;
    *(__nv_bfloat162*)(Xl + i)     = l01;
    *(__nv_bfloat162*)(Xl + i + 2) = l23;
}

// Transpose + split 1024x1024 weights: T[e][d] = W[d][e]
__global__ void __launch_bounds__(256)
transpose_split_kernel(const float* __restrict__ W0, const float* __restrict__ W1,
                       const float* __restrict__ W2,
                       __nv_bfloat16* __restrict__ T0h, __nv_bfloat16* __restrict__ T0l,
                       __nv_bfloat16* __restrict__ T1h, __nv_bfloat16* __restrict__ T1l,
                       __nv_bfloat16* __restrict__ T2h, __nv_bfloat16* __restrict__ T2l)
{
    __shared__ float t[32][33];
    const float* W = (blockIdx.z == 0) ? W0 : (blockIdx.z == 1) ? W1 : W2;
    __nv_bfloat16* Th = (blockIdx.z == 0) ? T0h : (blockIdx.z == 1) ? T1h : T2h;
    __nv_bfloat16* Tl = (blockIdx.z == 0) ? T0l : (blockIdx.z == 1) ? T1l : T2l;

    const int tx = threadIdx.x, ty = threadIdx.y;       // block 32x8
    const int e = blockIdx.x * 32 + tx;
    const int d0 = blockIdx.y * 32;
    #pragma unroll
    for (int i = ty; i < 32; i += 8)
        t[i][tx] = W[(long)(d0 + i) * D_ + e];
    __syncthreads();
    const int eo = blockIdx.x * 32;
    const int d = d0 + tx;
    #pragma unroll
    for (int i = ty; i < 32; i += 8) {
        float w = t[tx][i];
        __nv_bfloat16 h = __float2bfloat16(w);
        __nv_bfloat16 l = __float2bfloat16(w - __bfloat162float(h));
        Th[(long)(eo + i) * D_ + d] = h;
        Tl[(long)(eo + i) * D_ + d] = l;
    }
}

// Row softmax over S (length 2048), write split-bf16 P.
__global__ void __launch_bounds__(256)
softmax_split_kernel(const float* __restrict__ S, __nv_bfloat16* __restrict__ Ph,
                     __nv_bfloat16* __restrict__ Pl)
{
    const long row = blockIdx.x;
    const float* p = S + row * (long)N_;
    const int tid = threadIdx.x;

    float v[8];
    float mx = -1e30f;
    #pragma unroll
    for (int i = 0; i < 8; i++) { v[i] = p[tid + i * 256]; mx = fmaxf(mx, v[i]); }

    __shared__ float redm[8], reds[8];
    #pragma unroll
    for (int o = 16; o; o >>= 1) mx = fmaxf(mx, __shfl_xor_sync(0xffffffffu, mx, o));
    if ((tid & 31) == 0) redm[tid >> 5] = mx;
    __syncthreads();
    if (tid == 0) {
        float m = redm[0];
        #pragma unroll
        for (int i = 1; i < 8; i++) m = fmaxf(m, redm[i]);
        redm[0] = m;
    }
    __syncthreads();
    mx = redm[0];

    float s = 0.0f;
    #pragma unroll
    for (int i = 0; i < 8; i++) { v[i] = __expf(v[i] - mx); s += v[i]; }
    #pragma unroll
    for (int o = 16; o; o >>= 1) s += __shfl_xor_sync(0xffffffffu, s, o);
    if ((tid & 31) == 0) reds[tid >> 5] = s;
    __syncthreads();
    if (tid == 0) {
        float m = 0.0f;
        #pragma unroll
        for (int i = 0; i < 8; i++) m += reds[i];
        reds[0] = m;
    }
    __syncthreads();
    const float inv = 1.0f / reds[0];

    #pragma unroll
    for (int i = 0; i < 8; i++) {
        float w = v[i] * inv;
        __nv_bfloat16 h = __float2bfloat16(w);
        __nv_bfloat16 l = __float2bfloat16(w - __bfloat162float(h));
        Ph[row * (long)N_ + tid + i * 256] = h;
        Pl[row * (long)N_ + tid + i * 256] = l;
    }
}

// ================= host glue =================
extern "C" void kernel_launch(void* const* d_in, const int* in_sizes, int n_in,
                              void* d_out, int out_size)
{
    const float* X  = (const float*)d_in[0];
    const float* Wq = (const float*)d_in[1];
    const float* bq = (const float*)d_in[2];
    const float* Wk = (const float*)d_in[3];
    const float* bk = (const float*)d_in[4];
    const float* Wv = (const float*)d_in[5];
    const float* bv = (const float*)d_in[6];
    float* out = (float*)d_out;

    __nv_bfloat16 *Xh, *Xl, *Qh, *Ql, *Kh, *Kl, *Vth, *Vtl;
    __nv_bfloat16 *Wqth, *Wqtl, *Wkth, *Wktl, *Wvth, *Wvtl, *Ph, *Pl;
    float* S;
    cudaGetSymbolAddress((void**)&Xh, g_Xh);   cudaGetSymbolAddress((void**)&Xl, g_Xl);
    cudaGetSymbolAddress((void**)&Qh, g_Qh);   cudaGetSymbolAddress((void**)&Ql, g_Ql);
    cudaGetSymbolAddress((void**)&Kh, g_Kh);   cudaGetSymbolAddress((void**)&Kl, g_Kl);
    cudaGetSymbolAddress((void**)&Vth, g_Vth); cudaGetSymbolAddress((void**)&Vtl, g_Vtl);
    cudaGetSymbolAddress((void**)&Wqth, g_Wqth); cudaGetSymbolAddress((void**)&Wqtl, g_Wqtl);
    cudaGetSymbolAddress((void**)&Wkth, g_Wkth); cudaGetSymbolAddress((void**)&Wktl, g_Wktl);
    cudaGetSymbolAddress((void**)&Wvth, g_Wvth); cudaGetSymbolAddress((void**)&Wvtl, g_Wvtl);
    cudaGetSymbolAddress((void**)&Ph, g_Ph);   cudaGetSymbolAddress((void**)&Pl, g_Pl);
    cudaGetSymbolAddress((void**)&S, g_S);

    cudaFuncSetAttribute((const void*)tc_gemm<1, 1>, cudaFuncAttributeMaxDynamicSharedMemorySize, (int)SMEM_BYTES);
    cudaFuncSetAttribute((const void*)tc_gemm<1, 2>, cudaFuncAttributeMaxDynamicSharedMemorySize, (int)SMEM_BYTES);
    cudaFuncSetAttribute((const void*)tc_gemm<0, 0>, cudaFuncAttributeMaxDynamicSharedMemorySize, (int)SMEM_BYTES);

    dim3 blk(256);

    // 0) split X, transpose+split weights
    split_x_kernel<<<(MTOT * D_) / 1024, 256>>>(X, Xh, Xl);
    transpose_split_kernel<<<dim3(32, 32, 3), dim3(32, 8)>>>(
        Wq, Wk, Wv, Wqth, Wqtl, Wkth, Wktl, Wvth, Wvtl);

    // 1) Q = X Wq^T + bq ; K = X Wk^T + bk   (split-bf16 outputs)
    tc_gemm<1, 1><<<dim3(8, 64, 1), blk, SMEM_BYTES>>>(
        Xh, Xl, D_, 0, Wqth, Wqtl, D_, 0, nullptr, Qh, Ql, D_, 0, bq, D_);
    tc_gemm<1, 1><<<dim3(8, 64, 1), blk, SMEM_BYTES>>>(
        Xh, Xl, D_, 0, Wkth, Wktl, D_, 0, nullptr, Kh, Kl, D_, 0, bk, D_);
    // 1b) V^T[e,m] = Wv^T X^T + bv (bias by row e)
    tc_gemm<1, 2><<<dim3(64, 8, 1), blk, SMEM_BYTES>>>(
        Wvth, Wvtl, D_, 0, Xh, Xl, D_, 0, nullptr, Vth, Vtl, MTOT, 0, bv, D_);

    // 2) S = Q K^T per batch (fp32)
    tc_gemm<0, 0><<<dim3(16, 16, B_), blk, SMEM_BYTES>>>(
        Qh, Ql, D_, (long)N_ * D_, Kh, Kl, D_, (long)N_ * D_,
        S, nullptr, nullptr, N_, (long)N_ * N_, nullptr, D_);

    // 3) softmax + split P
    softmax_split_kernel<<<B_ * N_, 256>>>(S, Ph, Pl);

    // 4) out = P V per batch (NT against V^T, fp32 out)
    tc_gemm<0, 0><<<dim3(8, 16, B_), blk, SMEM_BYTES>>>(
        Ph, Pl, N_, (long)N_ * N_, Vth, Vtl, MTOT, (long)N_,
        out, nullptr, nullptr, D_, (long)N_ * D_, nullptr, N_);
}